// round 15
// baseline (speedup 1.0000x reference)
#include <cuda_runtime.h>
#include <cuda_bf16.h>

#define N_NODES 50000
#define N_EDGES 800000
#define D 64
#define NGEMM 391            // ceil(50000/128) gemm1 tiles
#define NEDGE 12500          // edge blocks (16 half-warp groups x 4 edges each)
#define NTOT  (NGEMM + NEDGE)

// ---- device-global scratch (no allocations allowed) ----
__device__ __align__(16) float g_denom[N_NODES];
__device__ __align__(16) float g_hunnorm[N_NODES * D];   // un-normalized msg sums

// ---------------------------------------------------------------------------
// Combined kernel: blocks with bid%33==0 (391 of them, spread through the
// launch so every wave mixes both kinds) run GEMM-1:
//     out[tile] = h_dst @ W1^T + b          (K = 0..63; edge-independent)
// All other blocks (12500) run the edge pass:
//     ex = exp(dot(h_src[src], e)); hunnorm[dst] += ex*hv; denom[dst] += ex
// GEMM-1 blocks are FMA-bound, edge blocks LTS-bound -> they overlap.
// ---------------------------------------------------------------------------
#define HT_STRIDE 132   // 128 + 4 pad
__global__ void __launch_bounds__(256) kgcn_edge_gemm1_kernel(
        const float* __restrict__ h_src,
        const float* __restrict__ e,
        const int* __restrict__ src,
        const int* __restrict__ dst,
        const float* __restrict__ h_dstp,
        const float* __restrict__ W,
        const float* __restrict__ b,
        float* __restrict__ out) {
    __shared__ float W_s[64 * 64];           // [k][j], W1 transposed (16KB)
    __shared__ float h_s[32 * HT_STRIDE];    // [kk][node] staged chunk (16.9KB)

    const int bid = blockIdx.x;
    const int q = bid / 33;
    const int r = bid - q * 33;

    if (r == 0) {
        // ---------------- GEMM-1 block: tile q ----------------
        const int tid = threadIdx.x;
        // W1 = W[:, 0:64] transposed: W_s[k*64 + j] = W[j*128 + k]
        for (int i = tid; i < 64 * 64; i += 256)
            W_s[(i & 63) * 64 + (i >> 6)] = W[(i >> 6) * 128 + (i & 63)];

        const int tx = tid & 15;      // cols  4*tx .. 4*tx+3
        const int ty = tid >> 4;      // nodes 8*ty .. 8*ty+7
        const int node0 = q * 128;

        float acc[8][4];
        #pragma unroll
        for (int n = 0; n < 8; n++)
            acc[n][0] = acc[n][1] = acc[n][2] = acc[n][3] = 0.f;

        #pragma unroll
        for (int c = 0; c < 2; c++) {
            const int kof4 = c * 8;
            __syncthreads();   // c==0 covers W_s; c==1 protects h_s reuse
            #pragma unroll
            for (int rr = 0; rr < 4; rr++) {
                int idx = tid + rr * 256;   // 0..1023
                int n   = idx >> 3;
                int qq  = idx & 7;
                int gn  = node0 + n;
                float4 v = make_float4(0.f, 0.f, 0.f, 0.f);
                if (gn < N_NODES)
                    v = reinterpret_cast<const float4*>(h_dstp)[(size_t)gn * 16 + kof4 + qq];
                h_s[(qq * 4 + 0) * HT_STRIDE + n] = v.x;
                h_s[(qq * 4 + 1) * HT_STRIDE + n] = v.y;
                h_s[(qq * 4 + 2) * HT_STRIDE + n] = v.z;
                h_s[(qq * 4 + 3) * HT_STRIDE + n] = v.w;
            }
            __syncthreads();

            const float* Wrow = &W_s[(c * 32) * 64 + 4 * tx];
            #pragma unroll 8
            for (int kk = 0; kk < 32; kk++) {
                float4 w  = *reinterpret_cast<const float4*>(Wrow + kk * 64);
                float4 ha = *reinterpret_cast<const float4*>(&h_s[kk * HT_STRIDE + 8 * ty]);
                float4 hb = *reinterpret_cast<const float4*>(&h_s[kk * HT_STRIDE + 8 * ty + 4]);
                float hn[8] = {ha.x, ha.y, ha.z, ha.w, hb.x, hb.y, hb.z, hb.w};
                #pragma unroll
                for (int n = 0; n < 8; n++) {
                    acc[n][0] = fmaf(hn[n], w.x, acc[n][0]);
                    acc[n][1] = fmaf(hn[n], w.y, acc[n][1]);
                    acc[n][2] = fmaf(hn[n], w.z, acc[n][2]);
                    acc[n][3] = fmaf(hn[n], w.w, acc[n][3]);
                }
            }
        }

        float4 bb = *reinterpret_cast<const float4*>(&b[4 * tx]);
        #pragma unroll
        for (int n = 0; n < 8; n++) {
            int gn = node0 + 8 * ty + n;
            if (gn < N_NODES) {
                float4 o = make_float4(acc[n][0] + bb.x, acc[n][1] + bb.y,
                                       acc[n][2] + bb.z, acc[n][3] + bb.w);
                reinterpret_cast<float4*>(out)[(size_t)gn * 16 + tx] = o;
            }
        }
        return;
    }

    // ---------------- edge block ----------------
    // edge ordinal: q*32 + (r-1)  (q<390 full; q==390 has r=1..20) -> 0..12499
    int eb_ord = q * 32 + (r - 1);
    int grp = eb_ord * 16 + (threadIdx.x >> 4);   // 0..199999
    int sub = threadIdx.x & 15;
    int eb  = grp * 4;

    int4 s4 = *reinterpret_cast<const int4*>(&src[eb]);
    int4 d4 = *reinterpret_cast<const int4*>(&dst[eb]);

    const float4* h4 = reinterpret_cast<const float4*>(h_src);
    const float4* e4 = reinterpret_cast<const float4*>(e);

    float4 ev0 = e4[(size_t)(eb + 0) * 16 + sub];
    float4 ev1 = e4[(size_t)(eb + 1) * 16 + sub];
    float4 ev2 = e4[(size_t)(eb + 2) * 16 + sub];
    float4 ev3 = e4[(size_t)(eb + 3) * 16 + sub];
    float4 hv0 = h4[(size_t)s4.x * 16 + sub];
    float4 hv1 = h4[(size_t)s4.y * 16 + sub];
    float4 hv2 = h4[(size_t)s4.z * 16 + sub];
    float4 hv3 = h4[(size_t)s4.w * 16 + sub];

    float t0 = hv0.x * ev0.x + hv0.y * ev0.y + hv0.z * ev0.z + hv0.w * ev0.w;
    float t1 = hv1.x * ev1.x + hv1.y * ev1.y + hv1.z * ev1.z + hv1.w * ev1.w;
    float t2 = hv2.x * ev2.x + hv2.y * ev2.y + hv2.z * ev2.z + hv2.w * ev2.w;
    float t3 = hv3.x * ev3.x + hv3.y * ev3.y + hv3.z * ev3.z + hv3.w * ev3.w;

    #pragma unroll
    for (int o = 1; o < 16; o <<= 1) {
        t0 += __shfl_xor_sync(0xffffffffu, t0, o);
        t1 += __shfl_xor_sync(0xffffffffu, t1, o);
        t2 += __shfl_xor_sync(0xffffffffu, t2, o);
        t3 += __shfl_xor_sync(0xffffffffu, t3, o);
    }

    float ex0 = __expf(t0);
    float ex1 = __expf(t1);
    float ex2 = __expf(t2);
    float ex3 = __expf(t3);

    float* a0 = &g_hunnorm[(size_t)d4.x * D + sub * 4];
    float* a1 = &g_hunnorm[(size_t)d4.y * D + sub * 4];
    float* a2 = &g_hunnorm[(size_t)d4.z * D + sub * 4];
    float* a3 = &g_hunnorm[(size_t)d4.w * D + sub * 4];
    asm volatile("red.global.add.v4.f32 [%0], {%1, %2, %3, %4};"
                 :: "l"(a0), "f"(ex0 * hv0.x), "f"(ex0 * hv0.y),
                    "f"(ex0 * hv0.z), "f"(ex0 * hv0.w) : "memory");
    asm volatile("red.global.add.v4.f32 [%0], {%1, %2, %3, %4};"
                 :: "l"(a1), "f"(ex1 * hv1.x), "f"(ex1 * hv1.y),
                    "f"(ex1 * hv1.z), "f"(ex1 * hv1.w) : "memory");
    asm volatile("red.global.add.v4.f32 [%0], {%1, %2, %3, %4};"
                 :: "l"(a2), "f"(ex2 * hv2.x), "f"(ex2 * hv2.y),
                    "f"(ex2 * hv2.z), "f"(ex2 * hv2.w) : "memory");
    asm volatile("red.global.add.v4.f32 [%0], {%1, %2, %3, %4};"
                 :: "l"(a3), "f"(ex3 * hv3.x), "f"(ex3 * hv3.y),
                    "f"(ex3 * hv3.z), "f"(ex3 * hv3.w) : "memory");
    if (sub == 0) {
        atomicAdd(&g_denom[d4.x], ex0);
        atomicAdd(&g_denom[d4.y], ex1);
        atomicAdd(&g_denom[d4.z], ex2);
        atomicAdd(&g_denom[d4.w], ex3);
    }
}

// ---------------------------------------------------------------------------
// GEMM-2: out += (hunnorm/denom) @ W2^T     (K = 64..127 of the concat)
// Same R11 structure, K=64 (2 chunks), accumulates into out.
// ---------------------------------------------------------------------------
__global__ void __launch_bounds__(256) kgcn_gemm2_kernel(
        const float* __restrict__ W,
        float* __restrict__ out) {
    __shared__ float W_s[64 * 64];           // [k][j], W2 transposed
    __shared__ float h_s[32 * HT_STRIDE];    // [kk][node]

    const int tid = threadIdx.x;
    // W2 = W[:, 64:128] transposed: W_s[k*64 + j] = W[j*128 + 64 + k]
    for (int i = tid; i < 64 * 64; i += 256)
        W_s[(i & 63) * 64 + (i >> 6)] = W[(i >> 6) * 128 + 64 + (i & 63)];

    const int tx = tid & 15;
    const int ty = tid >> 4;
    const int node0 = blockIdx.x * 128;

    float acc[8][4];
    #pragma unroll
    for (int n = 0; n < 8; n++)
        acc[n][0] = acc[n][1] = acc[n][2] = acc[n][3] = 0.f;

    #pragma unroll
    for (int c = 0; c < 2; c++) {
        const int kof4 = c * 8;
        __syncthreads();
        #pragma unroll
        for (int rr = 0; rr < 4; rr++) {
            int idx = tid + rr * 256;
            int n   = idx >> 3;
            int qq  = idx & 7;
            int gn  = node0 + n;
            float4 v = make_float4(0.f, 0.f, 0.f, 0.f);
            if (gn < N_NODES) {
                v = reinterpret_cast<const float4*>(g_hunnorm)[(size_t)gn * 16 + kof4 + qq];
                float dn = g_denom[gn];
                float inv = (dn != 0.f) ? (1.0f / dn) : 0.f;   // edge-less -> 0
                v.x *= inv; v.y *= inv; v.z *= inv; v.w *= inv;
            }
            h_s[(qq * 4 + 0) * HT_STRIDE + n] = v.x;
            h_s[(qq * 4 + 1) * HT_STRIDE + n] = v.y;
            h_s[(qq * 4 + 2) * HT_STRIDE + n] = v.z;
            h_s[(qq * 4 + 3) * HT_STRIDE + n] = v.w;
        }
        __syncthreads();

        const float* Wrow = &W_s[(c * 32) * 64 + 4 * tx];
        #pragma unroll 8
        for (int kk = 0; kk < 32; kk++) {
            float4 w  = *reinterpret_cast<const float4*>(Wrow + kk * 64);
            float4 ha = *reinterpret_cast<const float4*>(&h_s[kk * HT_STRIDE + 8 * ty]);
            float4 hb = *reinterpret_cast<const float4*>(&h_s[kk * HT_STRIDE + 8 * ty + 4]);
            float hn[8] = {ha.x, ha.y, ha.z, ha.w, hb.x, hb.y, hb.z, hb.w};
            #pragma unroll
            for (int n = 0; n < 8; n++) {
                acc[n][0] = fmaf(hn[n], w.x, acc[n][0]);
                acc[n][1] = fmaf(hn[n], w.y, acc[n][1]);
                acc[n][2] = fmaf(hn[n], w.z, acc[n][2]);
                acc[n][3] = fmaf(hn[n], w.w, acc[n][3]);
            }
        }
    }

    #pragma unroll
    for (int n = 0; n < 8; n++) {
        int gn = node0 + 8 * ty + n;
        if (gn < N_NODES) {
            float4 cur = reinterpret_cast<float4*>(out)[(size_t)gn * 16 + tx];
            float4 o = make_float4(cur.x + acc[n][0], cur.y + acc[n][1],
                                   cur.z + acc[n][2], cur.w + acc[n][3]);
            reinterpret_cast<float4*>(out)[(size_t)gn * 16 + tx] = o;
        }
    }
}

// ---------------------------------------------------------------------------
// Launch.  Inputs: 0 h_src, 1 h_dst, 2 e, 3 src, 4 dst, 5 W, 6 b
// ---------------------------------------------------------------------------
extern "C" void kernel_launch(void* const* d_in, const int* in_sizes, int n_in,
                              void* d_out, int out_size) {
    const float* h_src = (const float*)d_in[0];
    const float* h_dst = (const float*)d_in[1];
    const float* e     = (const float*)d_in[2];
    const int*   src   = (const int*)d_in[3];
    const int*   dst   = (const int*)d_in[4];
    const float* W     = (const float*)d_in[5];
    const float* b     = (const float*)d_in[6];
    float* out = (float*)d_out;

    void* p_hunnorm = nullptr;
    void* p_denom   = nullptr;
    cudaGetSymbolAddress(&p_hunnorm, g_hunnorm);
    cudaGetSymbolAddress(&p_denom,   g_denom);
    cudaMemsetAsync(p_hunnorm, 0, sizeof(float) * N_NODES * D);
    cudaMemsetAsync(p_denom,   0, sizeof(float) * N_NODES);

    // 12891 blocks: 391 interleaved GEMM-1 blocks + 12500 edge blocks
    kgcn_edge_gemm1_kernel<<<NTOT, 256>>>(h_src, e, src, dst, h_dst, W, b, out);
    kgcn_gemm2_kernel<<<NGEMM, 256>>>(W, out);
}

// round 16
// speedup vs baseline: 1.1262x; 1.1262x over previous
#include <cuda_runtime.h>
#include <cuda_bf16.h>

#define N_NODES 50000
#define N_EDGES 800000
#define D 64

// ---- device-global scratch (no allocations allowed) ----
__device__ __align__(16) float g_denom[N_NODES];
__device__ __align__(16) float g_hunnorm[N_NODES * D];   // un-normalized msg sums

// ---------------------------------------------------------------------------
// Fused edge kernel, 4 edges per half-warp (ILP=4). At the LTS traffic floor.
//   ex = exp(dot(h_src[src], e)); hunnorm[dst] += ex*hv (red.v4); denom += ex.
// ---------------------------------------------------------------------------
__global__ void __launch_bounds__(256) kgcn_edge_kernel(
        const float* __restrict__ h_src,
        const float* __restrict__ e,
        const int* __restrict__ src,
        const int* __restrict__ dst) {
    int tid = blockIdx.x * blockDim.x + threadIdx.x;
    int grp = tid >> 4;          // half-warp group id (200000 groups exactly)
    int sub = tid & 15;
    int eb  = grp * 4;

    int4 s4 = *reinterpret_cast<const int4*>(&src[eb]);
    int4 d4 = *reinterpret_cast<const int4*>(&dst[eb]);

    const float4* h4 = reinterpret_cast<const float4*>(h_src);
    const float4* e4 = reinterpret_cast<const float4*>(e);

    float4 ev0 = e4[(size_t)(eb + 0) * 16 + sub];
    float4 ev1 = e4[(size_t)(eb + 1) * 16 + sub];
    float4 ev2 = e4[(size_t)(eb + 2) * 16 + sub];
    float4 ev3 = e4[(size_t)(eb + 3) * 16 + sub];
    float4 hv0 = h4[(size_t)s4.x * 16 + sub];
    float4 hv1 = h4[(size_t)s4.y * 16 + sub];
    float4 hv2 = h4[(size_t)s4.z * 16 + sub];
    float4 hv3 = h4[(size_t)s4.w * 16 + sub];

    float t0 = hv0.x * ev0.x + hv0.y * ev0.y + hv0.z * ev0.z + hv0.w * ev0.w;
    float t1 = hv1.x * ev1.x + hv1.y * ev1.y + hv1.z * ev1.z + hv1.w * ev1.w;
    float t2 = hv2.x * ev2.x + hv2.y * ev2.y + hv2.z * ev2.z + hv2.w * ev2.w;
    float t3 = hv3.x * ev3.x + hv3.y * ev3.y + hv3.z * ev3.z + hv3.w * ev3.w;

    #pragma unroll
    for (int o = 1; o < 16; o <<= 1) {
        t0 += __shfl_xor_sync(0xffffffffu, t0, o);
        t1 += __shfl_xor_sync(0xffffffffu, t1, o);
        t2 += __shfl_xor_sync(0xffffffffu, t2, o);
        t3 += __shfl_xor_sync(0xffffffffu, t3, o);
    }

    float ex0 = __expf(t0);
    float ex1 = __expf(t1);
    float ex2 = __expf(t2);
    float ex3 = __expf(t3);

    float* a0 = &g_hunnorm[(size_t)d4.x * D + sub * 4];
    float* a1 = &g_hunnorm[(size_t)d4.y * D + sub * 4];
    float* a2 = &g_hunnorm[(size_t)d4.z * D + sub * 4];
    float* a3 = &g_hunnorm[(size_t)d4.w * D + sub * 4];
    asm volatile("red.global.add.v4.f32 [%0], {%1, %2, %3, %4};"
                 :: "l"(a0), "f"(ex0 * hv0.x), "f"(ex0 * hv0.y),
                    "f"(ex0 * hv0.z), "f"(ex0 * hv0.w) : "memory");
    asm volatile("red.global.add.v4.f32 [%0], {%1, %2, %3, %4};"
                 :: "l"(a1), "f"(ex1 * hv1.x), "f"(ex1 * hv1.y),
                    "f"(ex1 * hv1.z), "f"(ex1 * hv1.w) : "memory");
    asm volatile("red.global.add.v4.f32 [%0], {%1, %2, %3, %4};"
                 :: "l"(a2), "f"(ex2 * hv2.x), "f"(ex2 * hv2.y),
                    "f"(ex2 * hv2.z), "f"(ex2 * hv2.w) : "memory");
    asm volatile("red.global.add.v4.f32 [%0], {%1, %2, %3, %4};"
                 :: "l"(a3), "f"(ex3 * hv3.x), "f"(ex3 * hv3.y),
                    "f"(ex3 * hv3.z), "f"(ex3 * hv3.w) : "memory");
    if (sub == 0) {
        atomicAdd(&g_denom[d4.x], ex0);
        atomicAdd(&g_denom[d4.y], ex1);
        atomicAdd(&g_denom[d4.z], ex2);
        atomicAdd(&g_denom[d4.w], ex3);
    }
}

// ---------------------------------------------------------------------------
// Output GEMM v6: out = concat(h_dst, hunnorm/denom) @ W^T + b
// R11 structure (128-node x 64-col tile, thread 8n x 4c, transposed h_s)
// with two occupancy fixes:
//   - __launch_bounds__(256, 4): cap regs at 64 -> 4 blocks/SM (was 3 @ 80r)
//   - W staged per 64-k HALF (16KB instead of 32KB): smem 33KB, never caps
//     below the register limit. The half split aligns with the h_dst/h_sum
//     concat split, so each half pairs one W panel with one source tensor.
// ---------------------------------------------------------------------------
#define HT_STRIDE 132   // 128 + 4 pad, multiple of 4 for float4 alignment
__global__ void __launch_bounds__(256, 4) kgcn_out_kernel(
        const float* __restrict__ h_dst,
        const float* __restrict__ W,
        const float* __restrict__ b,
        float* __restrict__ out) {
    __shared__ float W_s[64 * 64];           // [k][j] for current half (16KB)
    __shared__ float h_s[32 * HT_STRIDE];    // [kk][node], padded (16.9KB)

    const int tid = threadIdx.x;
    const int tx = tid & 15;      // cols  4*tx .. 4*tx+3
    const int ty = tid >> 4;      // nodes 8*ty .. 8*ty+7
    const int node0 = blockIdx.x * 128;

    float acc[8][4];
    #pragma unroll
    for (int n = 0; n < 8; n++)
        acc[n][0] = acc[n][1] = acc[n][2] = acc[n][3] = 0.f;

    #pragma unroll
    for (int half = 0; half < 2; half++) {
        const float* srcp = (half == 0) ? h_dst : g_hunnorm;

        __syncthreads();   // previous half's W_s readers done
        // stage W half: W_s[k*64 + j] = W[j*128 + half*64 + k], k in 0..63
        for (int i = tid; i < 64 * 64; i += 256) {
            int k = i >> 6;
            int j = i & 63;
            W_s[k * 64 + j] = W[j * 128 + half * 64 + k];
        }

        #pragma unroll
        for (int cc = 0; cc < 2; cc++) {
            const int kof4 = cc * 8;

            __syncthreads();   // prev chunk h_s readers done; W_s write visible
            // Stage 128 nodes x 32 k, transposed: 1024 float4 loads, 4/thread.
            #pragma unroll
            for (int r = 0; r < 4; r++) {
                int idx = tid + r * 256;    // 0..1023
                int n   = idx >> 3;         // local node 0..127
                int q   = idx & 7;          // float4 k-slot 0..7
                int gn  = node0 + n;
                float4 v = make_float4(0.f, 0.f, 0.f, 0.f);
                if (gn < N_NODES) {
                    v = reinterpret_cast<const float4*>(srcp)[(size_t)gn * 16 + kof4 + q];
                    if (half == 1) {
                        float dn = g_denom[gn];
                        float inv = (dn != 0.f) ? (1.0f / dn) : 0.f;  // edge-less -> 0
                        v.x *= inv; v.y *= inv; v.z *= inv; v.w *= inv;
                    }
                }
                h_s[(q * 4 + 0) * HT_STRIDE + n] = v.x;
                h_s[(q * 4 + 1) * HT_STRIDE + n] = v.y;
                h_s[(q * 4 + 2) * HT_STRIDE + n] = v.z;
                h_s[(q * 4 + 3) * HT_STRIDE + n] = v.w;
            }
            __syncthreads();

            const float* Wrow = &W_s[(cc * 32) * 64 + 4 * tx];
            #pragma unroll 8
            for (int kk = 0; kk < 32; kk++) {
                float4 w  = *reinterpret_cast<const float4*>(Wrow + kk * 64);
                float4 ha = *reinterpret_cast<const float4*>(&h_s[kk * HT_STRIDE + 8 * ty]);
                float4 hb = *reinterpret_cast<const float4*>(&h_s[kk * HT_STRIDE + 8 * ty + 4]);
                float hn[8] = {ha.x, ha.y, ha.z, ha.w, hb.x, hb.y, hb.z, hb.w};
                #pragma unroll
                for (int n = 0; n < 8; n++) {
                    acc[n][0] = fmaf(hn[n], w.x, acc[n][0]);
                    acc[n][1] = fmaf(hn[n], w.y, acc[n][1]);
                    acc[n][2] = fmaf(hn[n], w.z, acc[n][2]);
                    acc[n][3] = fmaf(hn[n], w.w, acc[n][3]);
                }
            }
        }
    }

    float4 bb = *reinterpret_cast<const float4*>(&b[4 * tx]);
    #pragma unroll
    for (int n = 0; n < 8; n++) {
        int gn = node0 + 8 * ty + n;
        if (gn < N_NODES) {
            float4 o = make_float4(acc[n][0] + bb.x, acc[n][1] + bb.y,
                                   acc[n][2] + bb.z, acc[n][3] + bb.w);
            reinterpret_cast<float4*>(out)[(size_t)gn * 16 + tx] = o;
        }
    }
}

// ---------------------------------------------------------------------------
// Launch.  Inputs: 0 h_src, 1 h_dst, 2 e, 3 src, 4 dst, 5 W, 6 b
// ---------------------------------------------------------------------------
extern "C" void kernel_launch(void* const* d_in, const int* in_sizes, int n_in,
                              void* d_out, int out_size) {
    const float* h_src = (const float*)d_in[0];
    const float* h_dst = (const float*)d_in[1];
    const float* e     = (const float*)d_in[2];
    const int*   src   = (const int*)d_in[3];
    const int*   dst   = (const int*)d_in[4];
    const float* W     = (const float*)d_in[5];
    const float* b     = (const float*)d_in[6];
    float* out = (float*)d_out;

    void* p_hunnorm = nullptr;
    void* p_denom   = nullptr;
    cudaGetSymbolAddress(&p_hunnorm, g_hunnorm);
    cudaGetSymbolAddress(&p_denom,   g_denom);
    cudaMemsetAsync(p_hunnorm, 0, sizeof(float) * N_NODES * D);
    cudaMemsetAsync(p_denom,   0, sizeof(float) * N_NODES);

    // 200000 half-warp groups * 4 edges; 16 groups per 256-thread block
    kgcn_edge_kernel<<<12500, 256>>>(h_src, e, src, dst);
    // 391 blocks of 128 nodes
    kgcn_out_kernel<<<(N_NODES + 127) / 128, 256>>>(h_dst, W, b, out);
}